// round 4
// baseline (speedup 1.0000x reference)
#include <cuda_runtime.h>
#include <math.h>

// Problem constants
#define CC    128
#define HWSZ  262144      // 512*512
#define BK    512         // B*K
#define NNEG  7
#define PP    4096
#define TAUI  (1.0f/0.07f)

// GEMM tiling
#define QT     64         // queries per block
#define PTILE  128        // protos per block (single chunk)
#define PSTR   132        // padded k-major stride for p tile
#define NPT    (PP/PTILE) // 32 proto tiles

// Scratch (device globals — no allocation allowed)
__device__ float g_qn[BK*CC];      // normalized query vectors
__device__ float g_pmax[BK*NPT];   // per (query, ptile) max similarity

// ---- packed fp32x2 helpers (sm_100+) --------------------------------------
__device__ __forceinline__ void ffma2(unsigned long long& acc,
                                      unsigned long long a, unsigned long long b) {
    asm("fma.rn.f32x2 %0, %1, %2, %0;" : "+l"(acc) : "l"(a), "l"(b));
}
__device__ __forceinline__ unsigned long long dup2(float x) {
    unsigned long long r;
    asm("mov.b64 %0, {%1, %1};" : "=l"(r) : "f"(x));
    return r;
}
__device__ __forceinline__ float2 unpack2(unsigned long long v) {
    float2 r;
    asm("mov.b64 {%0, %1}, %2;" : "=f"(r.x), "=f"(r.y) : "l"(v));
    return r;
}

// ---------------------------------------------------------------------------
// Kernel 1: fused sim GEMM.  grid=(8,32), block=256
//   Block: gathers+normalizes 64 queries from qf (writes g_qn when by==0),
//   stages 128 protos k-major (norms computed during staging), then an
//   8q x 4p per-thread FFMA2 microtile; q LDS are warp-broadcast (free).
// ---------------------------------------------------------------------------
__global__ void k_gemm(const float* __restrict__ pool,
                       const float* __restrict__ qf,
                       const int*   __restrict__ qidx,
                       float* __restrict__ out) {
    extern __shared__ float sm[];
    float* q_t = sm;            // [128][QT]   k-major
    float* p_t = sm + CC * QT;  // [128][PSTR] k-major, padded
    __shared__ float psum[2 * PTILE];   // proto half sums of squares
    __shared__ float qpart[4 * QT];     // gather partial sums [seg][q]

    int t     = threadIdx.x;
    int qbase = blockIdx.x * QT;
    int pbase = blockIdx.y * PTILE;

    if (blockIdx.x == 0 && blockIdx.y == 0 && t == 0) out[0] = 0.0f;

    // ---- issue query gather loads (4 threads per query, 32 channels each) ----
    int gq = t >> 2, seg = t & 3;
    int q  = qbase + gq;
    int gidx = qidx[q];
    int gb   = q >> 6;
    const float* gsrc = qf + ((size_t)(gb * CC + seg * 32)) * HWSZ + (size_t)gidx;
    float gv[32];
    #pragma unroll
    for (int i = 0; i < 32; i++) gv[i] = gsrc[(size_t)i * HWSZ];

    // ---- stage proto tile (transposed) + per-half sumsq ----
    {
        int sp = t & 127, half = t >> 7;
        const float* src = pool + (size_t)(pbase + sp) * CC + half * 64;
        float ssp = 0.0f;
        #pragma unroll
        for (int i = 0; i < 16; i++) {
            float4 v = *(const float4*)(src + i * 4);
            ssp += v.x * v.x + v.y * v.y + v.z * v.z + v.w * v.w;
            int k0 = half * 64 + i * 4;
            p_t[(k0 + 0) * PSTR + sp] = v.x;
            p_t[(k0 + 1) * PSTR + sp] = v.y;
            p_t[(k0 + 2) * PSTR + sp] = v.z;
            p_t[(k0 + 3) * PSTR + sp] = v.w;
        }
        psum[half * PTILE + sp] = ssp;
    }

    // ---- query normalize -> q_t (and g_qn from the by==0 slice) ----
    {
        float ss = 0.0f;
        #pragma unroll
        for (int i = 0; i < 32; i++) ss += gv[i] * gv[i];
        qpart[seg * QT + gq] = ss;
    }
    __syncthreads();
    {
        float tot = qpart[0 * QT + gq] + qpart[1 * QT + gq]
                  + qpart[2 * QT + gq] + qpart[3 * QT + gq];
        float inv = 1.0f / fmaxf(sqrtf(tot), 1e-12f);
        #pragma unroll
        for (int i = 0; i < 32; i++) {
            float nv = gv[i] * inv;
            q_t[(seg * 32 + i) * QT + gq] = nv;
            if (blockIdx.y == 0) g_qn[q * CC + seg * 32 + i] = nv;
        }
    }
    __syncthreads();

    int qgrp = t >> 5;   // 0..7  (== warp id) -> queries 8*qgrp .. +7
    int pgrp = t & 31;   // 0..31             -> protos  4*pgrp .. +3

    unsigned long long acc[4][4];
    #pragma unroll
    for (int i = 0; i < 4; i++)
        #pragma unroll
        for (int j = 0; j < 4; j++) acc[i][j] = 0ull;

    const float* qp = q_t + 8 * qgrp;
    const float* pp = p_t + 4 * pgrp;
    #pragma unroll 4
    for (int k = 0; k < CC; k++) {
        ulonglong2 qa = *(const ulonglong2*)(qp + k * QT);      // (q0,q1),(q2,q3)  broadcast
        ulonglong2 qb = *(const ulonglong2*)(qp + k * QT + 4);  // (q4,q5),(q6,q7)  broadcast
        float4 pv = *(const float4*)(pp + k * PSTR);
        unsigned long long d0 = dup2(pv.x);
        unsigned long long d1 = dup2(pv.y);
        unsigned long long d2 = dup2(pv.z);
        unsigned long long d3 = dup2(pv.w);
        ffma2(acc[0][0], qa.x, d0); ffma2(acc[0][1], qa.x, d1);
        ffma2(acc[0][2], qa.x, d2); ffma2(acc[0][3], qa.x, d3);
        ffma2(acc[1][0], qa.y, d0); ffma2(acc[1][1], qa.y, d1);
        ffma2(acc[1][2], qa.y, d2); ffma2(acc[1][3], qa.y, d3);
        ffma2(acc[2][0], qb.x, d0); ffma2(acc[2][1], qb.x, d1);
        ffma2(acc[2][2], qb.x, d2); ffma2(acc[2][3], qb.x, d3);
        ffma2(acc[3][0], qb.y, d0); ffma2(acc[3][1], qb.y, d1);
        ffma2(acc[3][2], qb.y, d2); ffma2(acc[3][3], qb.y, d3);
    }

    // proto reciprocal norms from staged sums of squares
    float r[4];
    #pragma unroll
    for (int j = 0; j < 4; j++)
        r[j] = 1.0f / fmaxf(sqrtf(psum[4*pgrp + j] + psum[PTILE + 4*pgrp + j]), 1e-12f);

    float bv[8];
    #pragma unroll
    for (int i = 0; i < 8; i++) bv[i] = -3e38f;
    #pragma unroll
    for (int qi = 0; qi < 4; qi++)
        #pragma unroll
        for (int j = 0; j < 4; j++) {
            float2 a = unpack2(acc[qi][j]);
            bv[2*qi]   = fmaxf(bv[2*qi],   a.x * r[j]);
            bv[2*qi+1] = fmaxf(bv[2*qi+1], a.y * r[j]);
        }

    // lanes of this warp cover all 128 protos -> warp max gives tile max
    #pragma unroll
    for (int o = 16; o; o >>= 1)
        #pragma unroll
        for (int i = 0; i < 8; i++)
            bv[i] = fmaxf(bv[i], __shfl_down_sync(0xffffffffu, bv[i], o));

    if (pgrp == 0) {
        #pragma unroll
        for (int i = 0; i < 8; i++)
            g_pmax[(qbase + 8*qgrp + i) * NPT + blockIdx.y] = bv[i];
    }
}

// ---------------------------------------------------------------------------
// Kernel 2: negatives + softmax CE + mean.  grid=64, block=256 (warp=query)
// ---------------------------------------------------------------------------
__global__ void k_final(const float* __restrict__ neg, float* __restrict__ out) {
    int q    = blockIdx.x * 8 + (threadIdx.x >> 5);
    int lane = threadIdx.x & 31;

    float v = g_pmax[q * NPT + lane];          // NPT == 32: every lane valid
    #pragma unroll
    for (int o = 16; o; o >>= 1) v = fmaxf(v, __shfl_xor_sync(0xffffffffu, v, o));
    float l0 = v * TAUI;

    float4 qv = *(const float4*)(g_qn + (size_t)q * CC + lane * 4);

    float ln[NNEG];
    #pragma unroll
    for (int n = 0; n < NNEG; n++) {
        float4 nv = *(const float4*)(neg + ((size_t)q * NNEG + n) * CC + lane * 4);
        float dp = qv.x * nv.x + qv.y * nv.y + qv.z * nv.z + qv.w * nv.w;
        float ss = nv.x * nv.x + nv.y * nv.y + nv.z * nv.z + nv.w * nv.w;
        #pragma unroll
        for (int o = 16; o; o >>= 1) {
            dp += __shfl_xor_sync(0xffffffffu, dp, o);
            ss += __shfl_xor_sync(0xffffffffu, ss, o);
        }
        ln[n] = dp / fmaxf(sqrtf(ss), 1e-12f) * TAUI;
    }

    if (lane == 0) {
        float m = l0;
        #pragma unroll
        for (int n = 0; n < NNEG; n++) m = fmaxf(m, ln[n]);
        float se = expf(l0 - m);
        #pragma unroll
        for (int n = 0; n < NNEG; n++) se += expf(ln[n] - m);
        float loss = logf(se) + m - l0;          // = -(log_softmax[0])
        atomicAdd(out, loss * (1.0f / (float)BK));
    }
}

// ---------------------------------------------------------------------------
extern "C" void kernel_launch(void* const* d_in, const int* in_sizes, int n_in,
                              void* d_out, int out_size) {
    const float* qf   = (const float*)d_in[0];  // [8,128,512,512]
    const float* pool = (const float*)d_in[1];  // [4096,128]
    const float* neg  = (const float*)d_in[2];  // [8,64,7,128]
    const int*   qidx = (const int*)d_in[3];    // [8,64]
    float* out = (float*)d_out;

    const int smem_gemm = (CC * QT + CC * PSTR) * (int)sizeof(float); // 100352 B
    cudaFuncSetAttribute(k_gemm, cudaFuncAttributeMaxDynamicSharedMemorySize, smem_gemm);

    k_gemm<<<dim3(BK / QT, PP / PTILE), 256, smem_gemm>>>(pool, qf, qidx, out);
    k_final<<<BK / 8, 256>>>(neg, out);
}

// round 5
// speedup vs baseline: 1.2253x; 1.2253x over previous
#include <cuda_runtime.h>
#include <math.h>

// Problem constants
#define CC    128
#define HWSZ  262144      // 512*512
#define BK    512         // B*K
#define NNEG  7
#define PP    4096
#define TAUI  (1.0f/0.07f)

// GEMM tiling
#define QT     32         // queries per block tile
#define PTILE  256        // protos per block
#define PCHUNK 128        // protos staged in smem at once
#define PSTR   132        // padded k-major stride for p tile
#define NPT    (PP/PTILE) // 16 proto tiles
#define NBLK   ((BK/QT)*(PP/PTILE))   // 256 blocks
#define NWORK  (BK/8)                 // 64 worker blocks for the final phase

// Scratch (device globals — no allocation allowed)
__device__ float        g_qn[BK*CC];     // normalized query vectors
__device__ float        g_pmax[BK*NPT];  // per (query, ptile) max similarity
__device__ unsigned int g_cnt = 0;       // monotonic cross-launch barrier counter

// ---- packed fp32x2 helpers (sm_100+) --------------------------------------
__device__ __forceinline__ void ffma2(unsigned long long& acc,
                                      unsigned long long a, unsigned long long b) {
    asm("fma.rn.f32x2 %0, %1, %2, %0;" : "+l"(acc) : "l"(a), "l"(b));
}
__device__ __forceinline__ unsigned long long dup2(float x) {
    unsigned long long r;
    asm("mov.b64 %0, {%1, %1};" : "=l"(r) : "f"(x));
    return r;
}
__device__ __forceinline__ float2 unpack2(unsigned long long v) {
    float2 r;
    asm("mov.b64 {%0, %1}, %2;" : "=f"(r.x), "=f"(r.y) : "l"(v));
    return r;
}

// ---------------------------------------------------------------------------
// Single fused kernel.  grid=(16,16), block=256
//   Phase 1 (all 256 blocks): gather+normalize 32 queries from qf, stage
//     proto chunks (norms computed during staging), 8q x 2p FFMA2 microtile,
//     emit per-(q, ptile) max into g_pmax.  by==0 blocks also publish g_qn.
//   Barrier: monotonic counter; only worker blocks spin (deadlock-free).
//   Phase 2 (first 64 blocks): negatives + softmax CE + mean -> out.
// ---------------------------------------------------------------------------
__global__ void __launch_bounds__(256, 2)
k_fused(const float* __restrict__ pool,
        const float* __restrict__ qf,
        const int*   __restrict__ qidx,
        const float* __restrict__ neg,
        float* __restrict__ out) {
    extern __shared__ float sm[];
    float* q_t = sm;            // [128][QT]   k-major
    float* p_t = sm + CC * QT;  // [128][PSTR] k-major, padded
    __shared__ float psum[2 * PCHUNK];      // proto half sums of squares
    __shared__ float qpart[8 * QT];         // gather partial sums [seg][q]
    __shared__ unsigned int s_old;

    int t     = threadIdx.x;
    int flat  = blockIdx.y * 16 + blockIdx.x;
    int qbase = blockIdx.x * QT;
    int pbase = blockIdx.y * PTILE;

    if (flat == 0 && t == 0) out[0] = 0.0f;

    // ---- issue the query gather loads first (16 independent LDG, MLP=16) ----
    int gq = t & 31, seg = t >> 5;                 // q within tile, c-segment
    int gidx = qidx[qbase + gq];
    int gb   = (qbase + gq) >> 6;
    const float* gsrc = qf + ((size_t)(gb * CC + seg * 16)) * HWSZ + (size_t)gidx;
    float gv[16];
    #pragma unroll
    for (int i = 0; i < 16; i++) gv[i] = gsrc[(size_t)i * HWSZ];

    // ---- stage proto chunk 0 (transposed) + per-half sumsq ----
    int sp = t & 127, half = t >> 7;
    {
        const float* src = pool + (size_t)(pbase + sp) * CC + half * 64;
        float ssp = 0.0f;
        #pragma unroll
        for (int i = 0; i < 16; i++) {
            float4 v = *(const float4*)(src + i * 4);
            ssp += v.x * v.x + v.y * v.y + v.z * v.z + v.w * v.w;
            int k0 = half * 64 + i * 4;
            p_t[(k0 + 0) * PSTR + sp] = v.x;
            p_t[(k0 + 1) * PSTR + sp] = v.y;
            p_t[(k0 + 2) * PSTR + sp] = v.z;
            p_t[(k0 + 3) * PSTR + sp] = v.w;
        }
        psum[half * PCHUNK + sp] = ssp;
    }

    // ---- finish query gather: partial sumsq -> reduce -> normalized store ----
    {
        float ss = 0.0f;
        #pragma unroll
        for (int i = 0; i < 16; i++) ss += gv[i] * gv[i];
        qpart[seg * QT + gq] = ss;
    }
    __syncthreads();
    {
        float tot = 0.0f;
        #pragma unroll
        for (int s = 0; s < 8; s++) tot += qpart[s * QT + gq];
        float inv = 1.0f / fmaxf(sqrtf(tot), 1e-12f);
        #pragma unroll
        for (int i = 0; i < 16; i++) {
            float nv = gv[i] * inv;
            q_t[(seg * 16 + i) * QT + gq] = nv;   // lanes vary q: no conflicts
            if (blockIdx.y == 0) g_qn[(qbase + gq) * CC + seg * 16 + i] = nv;
        }
    }

    int qrow = t >> 6;   // 0..3  -> queries 8*qrow .. +7
    int pcol = t & 63;   // 0..63 -> protos  2*pcol, 2*pcol+1 (within chunk)

    float bv[8];
    #pragma unroll
    for (int i = 0; i < 8; i++) bv[i] = -3e38f;

    #pragma unroll
    for (int c = 0; c < PTILE / PCHUNK; c++) {
        if (c > 0) {
            __syncthreads();   // previous chunk fully consumed
            const float* src = pool + (size_t)(pbase + c * PCHUNK + sp) * CC + half * 64;
            float ssp = 0.0f;
            #pragma unroll
            for (int i = 0; i < 16; i++) {
                float4 v = *(const float4*)(src + i * 4);
                ssp += v.x * v.x + v.y * v.y + v.z * v.z + v.w * v.w;
                int k0 = half * 64 + i * 4;
                p_t[(k0 + 0) * PSTR + sp] = v.x;
                p_t[(k0 + 1) * PSTR + sp] = v.y;
                p_t[(k0 + 2) * PSTR + sp] = v.z;
                p_t[(k0 + 3) * PSTR + sp] = v.w;
            }
            psum[half * PCHUNK + sp] = ssp;
        }
        __syncthreads();

        unsigned long long acc[4][2];
        #pragma unroll
        for (int i = 0; i < 4; i++) { acc[i][0] = 0ull; acc[i][1] = 0ull; }

        const float* qp = q_t + 8 * qrow;
        const float* pp = p_t + 2 * pcol;
        #pragma unroll 8
        for (int k = 0; k < CC; k++) {
            ulonglong2 qa = *(const ulonglong2*)(qp + k * QT);      // broadcast
            ulonglong2 qb = *(const ulonglong2*)(qp + k * QT + 4);  // broadcast
            float2 pv = *(const float2*)(pp + k * PSTR);
            unsigned long long d0 = dup2(pv.x);
            unsigned long long d1 = dup2(pv.y);
            ffma2(acc[0][0], qa.x, d0); ffma2(acc[0][1], qa.x, d1);
            ffma2(acc[1][0], qa.y, d0); ffma2(acc[1][1], qa.y, d1);
            ffma2(acc[2][0], qb.x, d0); ffma2(acc[2][1], qb.x, d1);
            ffma2(acc[3][0], qb.y, d0); ffma2(acc[3][1], qb.y, d1);
        }

        // proto reciprocal norms from staged sums of squares
        float r0 = 1.0f / fmaxf(sqrtf(psum[2*pcol]   + psum[PCHUNK + 2*pcol]),   1e-12f);
        float r1 = 1.0f / fmaxf(sqrtf(psum[2*pcol+1] + psum[PCHUNK + 2*pcol+1]), 1e-12f);
        #pragma unroll
        for (int i = 0; i < 4; i++) {
            float2 a0 = unpack2(acc[i][0]);
            float2 a1 = unpack2(acc[i][1]);
            bv[2*i]   = fmaxf(bv[2*i],   fmaxf(a0.x * r0, a1.x * r1));
            bv[2*i+1] = fmaxf(bv[2*i+1], fmaxf(a0.y * r0, a1.y * r1));
        }
    }

    // max across the 32 lanes of each warp (warp shares qrow)
    #pragma unroll
    for (int o = 16; o; o >>= 1)
        #pragma unroll
        for (int i = 0; i < 8; i++)
            bv[i] = fmaxf(bv[i], __shfl_down_sync(0xffffffffu, bv[i], o));

    // combine the two warps sharing each qrow via smem, publish g_pmax
    __syncthreads();
    int w = t >> 5;
    if ((t & 31) == 0) {
        #pragma unroll
        for (int i = 0; i < 8; i++) q_t[w * 8 + i] = bv[i];
    }
    __syncthreads();
    if (t < 32) {
        int r = t >> 3, qi = t & 7;
        float m = fmaxf(q_t[(2*r) * 8 + qi], q_t[(2*r+1) * 8 + qi]);
        g_pmax[(qbase + 8*r + qi) * NPT + blockIdx.y] = m;
    }

    // ---- device-wide barrier (monotonic counter; only workers spin) ----
    __syncthreads();
    if (t == 0) {
        __threadfence();
        unsigned int old = atomicAdd(&g_cnt, 1u);
        s_old = old;
        if (flat < NWORK) {
            unsigned int target = ((old >> 8) << 8) + (unsigned int)NBLK;
            while (*((volatile unsigned int*)&g_cnt) < target) { }
        }
    }
    __syncthreads();
    if (flat >= NWORK) return;
    __threadfence();   // acquire g_pmax / g_qn / out-zero

    // ---- phase 2: negatives + softmax CE + mean (warp per query) ----
    {
        int q    = flat * 8 + (t >> 5);
        int lane = t & 31;

        float v = (lane < NPT) ? g_pmax[q * NPT + lane] : -3e38f;
        #pragma unroll
        for (int o = 16; o; o >>= 1) v = fmaxf(v, __shfl_xor_sync(0xffffffffu, v, o));
        float l0 = v * TAUI;

        float4 qv = *(const float4*)(g_qn + (size_t)q * CC + lane * 4);

        float ln[NNEG];
        #pragma unroll
        for (int n = 0; n < NNEG; n++) {
            float4 nv = *(const float4*)(neg + ((size_t)q * NNEG + n) * CC + lane * 4);
            float dp = qv.x * nv.x + qv.y * nv.y + qv.z * nv.z + qv.w * nv.w;
            float ss = nv.x * nv.x + nv.y * nv.y + nv.z * nv.z + nv.w * nv.w;
            #pragma unroll
            for (int o = 16; o; o >>= 1) {
                dp += __shfl_xor_sync(0xffffffffu, dp, o);
                ss += __shfl_xor_sync(0xffffffffu, ss, o);
            }
            ln[n] = dp / fmaxf(sqrtf(ss), 1e-12f) * TAUI;
        }

        if (lane == 0) {
            float m = l0;
            #pragma unroll
            for (int n = 0; n < NNEG; n++) m = fmaxf(m, ln[n]);
            float se = expf(l0 - m);
            #pragma unroll
            for (int n = 0; n < NNEG; n++) se += expf(ln[n] - m);
            float loss = logf(se) + m - l0;      // = -(log_softmax[0])
            atomicAdd(out, loss * (1.0f / (float)BK));
        }
    }
}

// ---------------------------------------------------------------------------
extern "C" void kernel_launch(void* const* d_in, const int* in_sizes, int n_in,
                              void* d_out, int out_size) {
    const float* qf   = (const float*)d_in[0];  // [8,128,512,512]
    const float* pool = (const float*)d_in[1];  // [4096,128]
    const float* neg  = (const float*)d_in[2];  // [8,64,7,128]
    const int*   qidx = (const int*)d_in[3];    // [8,64]
    float* out = (float*)d_out;

    const int smem = (CC * QT + CC * PSTR) * (int)sizeof(float); // 83968 B
    cudaFuncSetAttribute(k_fused, cudaFuncAttributeMaxDynamicSharedMemorySize, smem);

    k_fused<<<dim3(BK / QT, PP / PTILE), 256, smem>>>(pool, qf, qidx, neg, out);
}